// round 4
// baseline (speedup 1.0000x reference)
#include <cuda_runtime.h>
#include <math.h>
#include <stdint.h>

typedef unsigned long long ull;

// Problem constants
#define BATCH 1024
#define TT    256
#define FF    128
#define HH    256
#define GG    1024   // 4*H
#define OO    50

// ---------------------------------------------------------------------------
// Static device scratch (allocation-free per harness rules)
// ---------------------------------------------------------------------------
__device__ float g_xz[(size_t)TT * BATCH * GG];      // [t][b][h*4+gate] interleaved
__device__ float g_h0seq[(size_t)TT * BATCH * HH];   // [t][b][h]
__device__ float g_hbuf[2][BATCH * HH];              // double-buffered h state
__device__ unsigned g_barc = 0;
__device__ unsigned g_barg = 0;

// ---------------------------------------------------------------------------
// f32x2 packed helpers (PTX-only; ptxas never auto-fuses)
// ---------------------------------------------------------------------------
__device__ __forceinline__ void ffma2(ull& d, ull a, ull b) {
    asm("fma.rn.f32x2 %0, %1, %2, %0;" : "+l"(d) : "l"(a), "l"(b));
}
__device__ __forceinline__ ull dup2(float v) {
    ull r; asm("mov.b64 %0, {%1, %1};" : "=l"(r) : "f"(v)); return r;
}
__device__ __forceinline__ float2 upk(ull v) {
    float2 f; asm("mov.b64 {%0, %1}, %2;" : "=f"(f.x), "=f"(f.y) : "l"(v)); return f;
}

// ---------------------------------------------------------------------------
// Grid-wide barrier (proven in R2; 256 blocks all resident by construction)
// ---------------------------------------------------------------------------
__device__ __forceinline__ void gbar() {
    __syncthreads();
    if (threadIdx.x == 0) {
        __threadfence();
        unsigned gen = *((volatile unsigned*)&g_barg);
        if (atomicAdd(&g_barc, 1) == gridDim.x - 1) {
            atomicExch(&g_barc, 0);
            __threadfence();
            atomicExch(&g_barg, gen + 1);
        } else {
            while (*((volatile unsigned*)&g_barg) == gen) { __nanosleep(32); }
        }
        __threadfence();
    }
    __syncthreads();
}

__device__ __forceinline__ float sigf(float x) { return 1.0f / (1.0f + expf(-x)); }

// ---------------------------------------------------------------------------
// SGEMM + bias, f32x2: C = A[M,K] @ B[K,1024] + bias, output INTERLEAVED cols
// (global col n = gate*256+h  ->  output col h*4+gate, contiguous per block).
// Block: 128 rows x 64 local cols (16 h x 4 gates), BK=16, 256 threads,
// micro 8x4 via 4 row-pairs. PERM remaps rows m=b*T+t -> t*B+b (layer 0).
// ---------------------------------------------------------------------------
template<bool PERM>
__global__ __launch_bounds__(256) void sgemm_bias(
    const float* __restrict__ A, const float* __restrict__ Bm,
    const float* __restrict__ bias, float* __restrict__ C,
    int M, int K)
{
    __shared__ __align__(16) float As[16 * 132];   // [k][m] transposed, padded
    __shared__ __align__(16) float Bs2[16 * 128];  // [k][64 cols duplicated]

    const int tid  = threadIdx.x;
    const int lane = tid & 31;
    const int w    = tid >> 5;
    // warp-internal 8x4 layout: keeps every LDS.128 single-phase
    const int tx = (lane & 7) | ((w & 1) << 3);       // 0..15 (h index)
    const int ty = ((lane >> 3) & 3) | ((w >> 1) << 2); // 0..15 (row-group)

    const int m0    = blockIdx.y * 128;
    const int hbase = blockIdx.x * 16;                // 16 h per block

    ull acc[4][4];
#pragma unroll
    for (int i = 0; i < 4; ++i)
#pragma unroll
        for (int j = 0; j < 4; ++j) acc[i][j] = 0ull;

    for (int k0 = 0; k0 < K; k0 += 16) {
        // A tile 128x16 -> As[k][m] (2 float4 per thread)
#pragma unroll
        for (int q = 0; q < 2; ++q) {
            int f4 = tid * 2 + q;
            int r  = f4 >> 2;
            int c4 = (f4 & 3) * 4;
            float4 v = *(const float4*)(A + (size_t)(m0 + r) * K + k0 + c4);
            As[(c4 + 0) * 132 + r] = v.x;
            As[(c4 + 1) * 132 + r] = v.y;
            As[(c4 + 2) * 132 + r] = v.z;
            As[(c4 + 3) * 132 + r] = v.w;
        }
        // B tile: gather 4 gates of h=(hbase+i0), store duplicated
        {
            int r  = tid >> 4;        // k row 0..15
            int i0 = tid & 15;        // h index 0..15
            const float* brow = Bm + (size_t)(k0 + r) * GG + hbase + i0;
            float v0 = brow[0];
            float v1 = brow[256];
            float v2 = brow[512];
            float v3 = brow[768];
            float4 d0 = make_float4(v0, v0, v1, v1);
            float4 d1 = make_float4(v2, v2, v3, v3);
            *(float4*)(Bs2 + r * 128 + i0 * 8)     = d0;
            *(float4*)(Bs2 + r * 128 + i0 * 8 + 4) = d1;
        }
        __syncthreads();

#pragma unroll
        for (int kk = 0; kk < 16; ++kk) {
            ulonglong2 aA = *(const ulonglong2*)(As  + kk * 132 + ty * 8);
            ulonglong2 aB = *(const ulonglong2*)(As  + kk * 132 + ty * 8 + 4);
            ulonglong2 b0 = *(const ulonglong2*)(Bs2 + kk * 128 + tx * 8);
            ulonglong2 b1 = *(const ulonglong2*)(Bs2 + kk * 128 + tx * 8 + 4);
            ull ap[4] = {aA.x, aA.y, aB.x, aB.y};
            ull bp[4] = {b0.x, b0.y, b1.x, b1.y};
#pragma unroll
            for (int i = 0; i < 4; ++i) {
                ffma2(acc[i][0], ap[i], bp[0]);
                ffma2(acc[i][1], ap[i], bp[1]);
                ffma2(acc[i][2], ap[i], bp[2]);
                ffma2(acc[i][3], ap[i], bp[3]);
            }
        }
        __syncthreads();
    }

    // bias for local cols c = tx*4 + g  (global n = g*256 + hbase + tx)
    float bb0 = bias[0 * 256 + hbase + tx];
    float bb1 = bias[1 * 256 + hbase + tx];
    float bb2 = bias[2 * 256 + hbase + tx];
    float bb3 = bias[3 * 256 + hbase + tx];

    const int ocol = hbase * 4 + tx * 4;   // interleaved output col (contiguous)
#pragma unroll
    for (int i = 0; i < 4; ++i) {
        float2 c0 = upk(acc[i][0]);
        float2 c1 = upk(acc[i][1]);
        float2 c2 = upk(acc[i][2]);
        float2 c3 = upk(acc[i][3]);
        size_t m = (size_t)(m0 + ty * 8 + 2 * i);
#pragma unroll
        for (int p = 0; p < 2; ++p) {
            size_t mm = m + p;
            size_t orow = PERM ? ((mm & (TT - 1)) * (size_t)BATCH + (mm >> 8)) : mm;
            float4 o;
            o.x = (p ? c0.y : c0.x) + bb0;
            o.y = (p ? c1.y : c1.x) + bb1;
            o.z = (p ? c2.y : c2.x) + bb2;
            o.w = (p ? c3.y : c3.x) + bb3;
            *(float4*)(C + orow * (size_t)GG + ocol) = o;
        }
    }
}

// ---------------------------------------------------------------------------
// Persistent LSTM layer, f32x2. Grid = 256 blocks (16 batch x 16 h chunks),
// 256 threads. Block tile: 64 batch rows x 64 cols (16 h x 4 gates).
// U gate-interleaved in SMEM for the whole layer; h chunks double-buffered
// and stored DUPLICATED so broadcast pairs are single LDS.128.
// Thread owns 4 rows x 1 h (all 4 gates) -> cell update fully in registers.
// ---------------------------------------------------------------------------
__global__ __launch_bounds__(256, 2) void lstm_rec(
    const float* __restrict__ xz,     // [T][B][h*4+gate]
    const float* __restrict__ U,      // [H][G] row-major (gate-major cols)
    float* __restrict__ seqout)       // [T][B][H] or nullptr
{
    extern __shared__ __align__(16) float sm[];
    float* Us2 = sm;                  // 256 x 64  (cols = h_l*4+gate)   64 KB
    float* h2a = Us2 + 256 * 64;      // 32 k x 128 (rows duplicated)    16 KB
    float* h2b = h2a + 32 * 128;      //                                 16 KB

    const int tid  = threadIdx.x;
    const int lane = tid & 31;
    const int w    = tid >> 5;
    const int tx = (lane & 7) | ((w & 1) << 3);         // 0..15 h index
    const int ty = ((lane >> 3) & 3) | ((w >> 1) << 2); // 0..15 row group

    const int bi = blockIdx.x >> 4;   // batch chunk
    const int hj = blockIdx.x & 15;   // hidden chunk

    // U slice, gate-interleaved: Us2[k][hl*4+g] = U[k][g*256 + hj*16 + hl]
    for (int idx = tid; idx < 256 * 64; idx += 256) {
        int k = idx >> 6, c = idx & 63;
        int g = c & 3, hl = c >> 2;
        Us2[idx] = U[(size_t)k * GG + g * HH + hj * 16 + hl];
    }
    // Zero this block's portion of h-state buffer 0
    {
        int r = tid >> 2, q = tid & 3;
        *(float4*)(&g_hbuf[0][(size_t)(bi * 64 + r) * HH + hj * 16 + q * 4]) =
            make_float4(0.f, 0.f, 0.f, 0.f);
    }
    gbar();

    const int row0 = ty * 4;              // local rows row0..row0+3
    const int colh = hj * 16 + tx;        // global h column
    const int fr   = tid >> 2;            // fill: row 0..63
    const int fk   = (tid & 3) * 8;       // fill: k offset

    float cst[4] = {0.f, 0.f, 0.f, 0.f};  // cell state (registers)

    for (int t = 0; t < TT; ++t) {
        const float* hin  = g_hbuf[t & 1];
        float*       hout = g_hbuf[(t + 1) & 1];

        // prefetch xz (consumed in epilogue; latency hidden by GEMM)
        float4 xz4[4];
#pragma unroll
        for (int r = 0; r < 4; ++r)
            xz4[r] = *(const float4*)(xz +
                ((size_t)t * BATCH + bi * 64 + row0 + r) * GG + colh * 4);

        // fill chunk 0
        {
            const float* src = hin + (size_t)(bi * 64 + fr) * HH + fk;
            float4 v0 = *(const float4*)(src);
            float4 v1 = *(const float4*)(src + 4);
            float* d = h2a + fk * 128 + 2 * fr;
            *(ull*)(d + 0 * 128) = dup2(v0.x); *(ull*)(d + 1 * 128) = dup2(v0.y);
            *(ull*)(d + 2 * 128) = dup2(v0.z); *(ull*)(d + 3 * 128) = dup2(v0.w);
            *(ull*)(d + 4 * 128) = dup2(v1.x); *(ull*)(d + 5 * 128) = dup2(v1.y);
            *(ull*)(d + 6 * 128) = dup2(v1.z); *(ull*)(d + 7 * 128) = dup2(v1.w);
        }
        __syncthreads();

        ull acc[4][2];
#pragma unroll
        for (int r = 0; r < 4; ++r) { acc[r][0] = 0ull; acc[r][1] = 0ull; }

        for (int c = 0; c < 8; ++c) {
            float* cur = (c & 1) ? h2b : h2a;
            float* nxt = (c & 1) ? h2a : h2b;
            float4 p0, p1;
            if (c < 7) {   // prefetch next chunk
                const float* src = hin + (size_t)(bi * 64 + fr) * HH + (c + 1) * 32 + fk;
                p0 = *(const float4*)(src);
                p1 = *(const float4*)(src + 4);
            }
            const float* us = Us2 + (c * 32) * 64;
#pragma unroll
            for (int kk = 0; kk < 32; ++kk) {
                ulonglong2 aA = *(const ulonglong2*)(cur + kk * 128 + ty * 8);
                ulonglong2 aB = *(const ulonglong2*)(cur + kk * 128 + ty * 8 + 4);
                ulonglong2 bv = *(const ulonglong2*)(us + kk * 64 + tx * 4);
                ffma2(acc[0][0], aA.x, bv.x); ffma2(acc[0][1], aA.x, bv.y);
                ffma2(acc[1][0], aA.y, bv.x); ffma2(acc[1][1], aA.y, bv.y);
                ffma2(acc[2][0], aB.x, bv.x); ffma2(acc[2][1], aB.x, bv.y);
                ffma2(acc[3][0], aB.y, bv.x); ffma2(acc[3][1], aB.y, bv.y);
            }
            if (c < 7) {
                float* d = nxt + fk * 128 + 2 * fr;
                *(ull*)(d + 0 * 128) = dup2(p0.x); *(ull*)(d + 1 * 128) = dup2(p0.y);
                *(ull*)(d + 2 * 128) = dup2(p0.z); *(ull*)(d + 3 * 128) = dup2(p0.w);
                *(ull*)(d + 4 * 128) = dup2(p1.x); *(ull*)(d + 5 * 128) = dup2(p1.y);
                *(ull*)(d + 6 * 128) = dup2(p1.z); *(ull*)(d + 7 * 128) = dup2(p1.w);
                __syncthreads();
            }
        }

        // epilogue: gates in registers (cols are i,f,g,o of h=colh)
#pragma unroll
        for (int r = 0; r < 4; ++r) {
            float2 zif = upk(acc[r][0]);
            float2 zgo = upk(acc[r][1]);
            float zi = zif.x + xz4[r].x;
            float zf = zif.y + xz4[r].y;
            float zg = zgo.x + xz4[r].z;
            float zo = zgo.y + xz4[r].w;
            float cc = sigf(zf) * cst[r] + sigf(zi) * tanhf(zg);
            cst[r] = cc;
            float hh = sigf(zo) * tanhf(cc);
            int bg = bi * 64 + row0 + r;
            hout[(size_t)bg * HH + colh] = hh;
            if (seqout) seqout[((size_t)t * BATCH + bg) * HH + colh] = hh;
        }
        gbar();   // publish h for next step
    }
    // final h (t=255) lives in g_hbuf[0]
}

// ---------------------------------------------------------------------------
// Head: logits = h @ Wout + bout; softmax; capped-simplex water-filling
// (bit-faithful: exact !=0.1f mask, freeze-on-done, 50 iters). Unchanged (R2).
// ---------------------------------------------------------------------------
__device__ __forceinline__ float clip01(float x) {
    return fminf(fmaxf(x, 0.0f), 0.1f);
}
__device__ __forceinline__ float wsum(float v) {
#pragma unroll
    for (int o = 16; o > 0; o >>= 1) v += __shfl_xor_sync(0xffffffffu, v, o);
    return v;
}
__device__ __forceinline__ float wmax(float v) {
#pragma unroll
    for (int o = 16; o > 0; o >>= 1) v = fmaxf(v, __shfl_xor_sync(0xffffffffu, v, o));
    return v;
}

__global__ __launch_bounds__(64) void head_kernel(
    const float* __restrict__ Wout, const float* __restrict__ bout,
    float* __restrict__ out)
{
    __shared__ float hsh[HH];
    __shared__ float lg[OO];
    const int b = blockIdx.x;
    const int tid = threadIdx.x;

    for (int i = tid; i < HH; i += 64) hsh[i] = g_hbuf[0][(size_t)b * HH + i];
    __syncthreads();

    if (tid < OO) {
        float a = bout[tid];
        for (int k = 0; k < HH; ++k) a = fmaf(hsh[k], Wout[(size_t)k * OO + tid], a);
        lg[tid] = a;
    }
    __syncthreads();

    if (tid < 32) {
        const bool has1 = (tid + 32) < OO;
        float v0 = lg[tid];
        float v1 = has1 ? lg[tid + 32] : -INFINITY;

        float m  = wmax(fmaxf(v0, v1));
        float e0 = expf(v0 - m);
        float e1 = has1 ? expf(v1 - m) : 0.0f;
        float s  = wsum(e0 + e1);
        float w0 = e0 / s, w1 = e1 / s;

        float old0 = w0, old1 = w1;
        float wc0 = clip01(w0), wc1 = clip01(w1);
        bool done = false;

        for (int it = 0; it < 50; ++it) {
            float leftover = wsum((old0 - wc0) + (old1 - wc1));
            bool m0 = (wc0 != 0.1f), m1 = (wc1 != 0.1f);
            float n0 = m0 ? wc0 : 0.0f;
            float n1 = m1 ? wc1 : 0.0f;
            float denom = wsum(n0 + n1);
            float dd = (denom == 0.0f) ? 1.0f : denom;
            float wn0 = m0 ? wc0 + leftover * n0 / dd : wc0;
            float wn1 = m1 ? wc1 + leftover * n1 / dd : wc1;
            bool over = __any_sync(0xffffffffu, (wn0 > 0.1f) || (wn1 > 0.1f));
            bool ndone = !over;
            float wx0 = ndone ? wn0 : clip01(wn0);
            float wx1 = ndone ? wn1 : clip01(wn1);
            if (!done) { old0 = wn0; old1 = wn1; wc0 = wx0; wc1 = wx1; }
            done = done || ndone;
        }

        out[(size_t)b * OO + tid] = wc0;
        if (has1) out[(size_t)b * OO + tid + 32] = wc1;
    }
}

// ---------------------------------------------------------------------------
// Launch (graph-capturable: kernel launches only)
// ---------------------------------------------------------------------------
extern "C" void kernel_launch(void* const* d_in, const int* in_sizes, int n_in,
                              void* d_out, int out_size)
{
    const float* x    = (const float*)d_in[0];
    const float* W0   = (const float*)d_in[1];
    const float* U0   = (const float*)d_in[2];
    const float* b0   = (const float*)d_in[3];
    const float* W1   = (const float*)d_in[4];
    const float* U1   = (const float*)d_in[5];
    const float* b1   = (const float*)d_in[6];
    const float* Wout = (const float*)d_in[7];
    const float* bout = (const float*)d_in[8];
    float* out = (float*)d_out;

    float *p_xz = nullptr, *p_h0 = nullptr;
    cudaGetSymbolAddress((void**)&p_xz, g_xz);
    cudaGetSymbolAddress((void**)&p_h0, g_h0seq);

    const int REC_SMEM = (256 * 64 + 2 * 32 * 128) * (int)sizeof(float); // 98304
    cudaFuncSetAttribute(lstm_rec, cudaFuncAttributeMaxDynamicSharedMemorySize, REC_SMEM);

    dim3 gg(16, (BATCH * TT) / 128);   // (16, 2048)

    // Layer 0 input projection: xz0[t][b][h*4+g]
    sgemm_bias<true><<<gg, 256>>>(x, W0, b0, p_xz, BATCH * TT, FF);
    // Layer 0 recurrence -> h0seq[t][b][h]
    lstm_rec<<<256, 256, REC_SMEM>>>(p_xz, U0, p_h0);
    // Layer 1 input projection (reuses g_xz)
    sgemm_bias<false><<<gg, 256>>>(p_h0, W1, b1, p_xz, BATCH * TT, HH);
    // Layer 1 recurrence (final h ends in g_hbuf[0])
    lstm_rec<<<256, 256, REC_SMEM>>>(p_xz, U1, nullptr);
    // Head: logits -> softmax -> rebalance
    head_kernel<<<BATCH, 64>>>(Wout, bout, out);
}

// round 5
// speedup vs baseline: 1.3922x; 1.3922x over previous
#include <cuda_runtime.h>
#include <math.h>
#include <stdint.h>

// Problem constants
#define BATCH 1024
#define TT    256
#define FF    128
#define HH    256
#define GG    1024   // 4*H
#define OO    50

// ---------------------------------------------------------------------------
// Static device scratch (allocation-free per harness rules)
// ---------------------------------------------------------------------------
__device__ float g_xz[(size_t)TT * BATCH * GG];      // [t][b][g]; reused L0 then L1
__device__ float g_h0seq[(size_t)TT * BATCH * HH];   // [t][b][h]
__device__ float g_hbuf[2][BATCH * HH];              // double-buffered h state
__device__ unsigned g_barc = 0;
__device__ unsigned g_barg = 0;

// ---------------------------------------------------------------------------
// Grid-wide barrier (proven in R2)
// ---------------------------------------------------------------------------
__device__ __forceinline__ void gbar() {
    __syncthreads();
    if (threadIdx.x == 0) {
        __threadfence();
        unsigned gen = *((volatile unsigned*)&g_barg);
        if (atomicAdd(&g_barc, 1) == gridDim.x - 1) {
            atomicExch(&g_barc, 0);
            __threadfence();
            atomicExch(&g_barg, gen + 1);
        } else {
            while (*((volatile unsigned*)&g_barg) == gen) { __nanosleep(32); }
        }
        __threadfence();
    }
    __syncthreads();
}

__device__ __forceinline__ float sigf(float x) { return 1.0f / (1.0f + expf(-x)); }

// ---------------------------------------------------------------------------
// tf32 helpers
// ---------------------------------------------------------------------------
__device__ __forceinline__ unsigned t32(float v) {
    unsigned r; asm("cvt.rna.tf32.f32 %0, %1;" : "=r"(r) : "f"(v)); return r;
}
__device__ __forceinline__ void split32(float v, unsigned& hi, unsigned& lo) {
    hi = t32(v);
    float l = v - __uint_as_float(hi);   // exact in fp32
    lo = t32(l);
}
__device__ __forceinline__ void mma_tf32(float* c, const unsigned* a, const unsigned* b) {
    asm volatile(
        "mma.sync.aligned.m16n8k8.row.col.f32.tf32.tf32.f32 "
        "{%0,%1,%2,%3}, {%4,%5,%6,%7}, {%8,%9}, {%0,%1,%2,%3};"
        : "+f"(c[0]), "+f"(c[1]), "+f"(c[2]), "+f"(c[3])
        : "r"(a[0]), "r"(a[1]), "r"(a[2]), "r"(a[3]), "r"(b[0]), "r"(b[1]));
}

// ---------------------------------------------------------------------------
// GEMM + bias via 3-term split-tf32 mma.sync (fp32-accurate).
// C[M,1024] = A[M,K] @ B[K,1024] + bias.  Block tile 128x64, BK=16,
// 256 threads = 8 warps as 4(M) x 2(N), warp tile 32x32.
// PERM=true remaps output rows m=b*T+t -> t*B+b (layer-0 xz layout).
// SMEM planes (hi/lo separate) with conflict-free permutation strides.
// ---------------------------------------------------------------------------
template<bool PERM>
__global__ __launch_bounds__(256) void gemm_tf32(
    const float* __restrict__ A, const float* __restrict__ Bm,
    const float* __restrict__ bias, float* __restrict__ C, int K)
{
    __shared__ __align__(16) unsigned As_h[128 * 20];  // [m][k] stride 20
    __shared__ __align__(16) unsigned As_l[128 * 20];
    __shared__ __align__(16) unsigned Bs_h[16 * 72];   // [k][n] stride 72
    __shared__ __align__(16) unsigned Bs_l[16 * 72];

    const int tid  = threadIdx.x;
    const int lane = tid & 31;
    const int w    = tid >> 5;
    const int wm   = w & 3;          // 0..3 -> rows wm*32
    const int wn   = w >> 2;         // 0..1 -> cols wn*32
    const int m0   = blockIdx.y * 128;
    const int n0   = blockIdx.x * 64;

    // global-load assignments
    const int aRow = tid >> 1;               // 0..127 (2 float4 per row pair)
    const int aC4  = (tid & 1) * 8;          // this thread loads k offsets aC4..aC4+7
    const int bRow = tid >> 4;               // 0..15
    const int bC4  = (tid & 15) * 4;         // n offset

    float acc[2][4][4];
#pragma unroll
    for (int i = 0; i < 2; ++i)
#pragma unroll
        for (int j = 0; j < 4; ++j)
#pragma unroll
            for (int r = 0; r < 4; ++r) acc[i][j][r] = 0.0f;

    const int iters = K >> 4;

    // prefetch tile 0
    float4 ar0 = *(const float4*)(A + (size_t)(m0 + aRow) * K + aC4);
    float4 ar1 = *(const float4*)(A + (size_t)(m0 + aRow) * K + aC4 + 4);
    float4 br  = *(const float4*)(Bm + (size_t)bRow * GG + n0 + bC4);

    for (int it = 0; it < iters; ++it) {
        // split + STS
        {
            unsigned h0, h1, h2, h3, l0, l1, l2, l3;
            split32(ar0.x, h0, l0); split32(ar0.y, h1, l1);
            split32(ar0.z, h2, l2); split32(ar0.w, h3, l3);
            *(uint4*)&As_h[aRow * 20 + aC4]     = make_uint4(h0, h1, h2, h3);
            *(uint4*)&As_l[aRow * 20 + aC4]     = make_uint4(l0, l1, l2, l3);
            split32(ar1.x, h0, l0); split32(ar1.y, h1, l1);
            split32(ar1.z, h2, l2); split32(ar1.w, h3, l3);
            *(uint4*)&As_h[aRow * 20 + aC4 + 4] = make_uint4(h0, h1, h2, h3);
            *(uint4*)&As_l[aRow * 20 + aC4 + 4] = make_uint4(l0, l1, l2, l3);
            split32(br.x, h0, l0); split32(br.y, h1, l1);
            split32(br.z, h2, l2); split32(br.w, h3, l3);
            *(uint4*)&Bs_h[bRow * 72 + bC4]     = make_uint4(h0, h1, h2, h3);
            *(uint4*)&Bs_l[bRow * 72 + bC4]     = make_uint4(l0, l1, l2, l3);
        }
        __syncthreads();

        if (it + 1 < iters) {   // prefetch next tile (latency hidden by mma)
            ar0 = *(const float4*)(A + (size_t)(m0 + aRow) * K + (it + 1) * 16 + aC4);
            ar1 = *(const float4*)(A + (size_t)(m0 + aRow) * K + (it + 1) * 16 + aC4 + 4);
            br  = *(const float4*)(Bm + (size_t)((it + 1) * 16 + bRow) * GG + n0 + bC4);
        }

#pragma unroll
        for (int s = 0; s < 2; ++s) {        // two k8 steps per BK=16
            unsigned ah[2][4], al[2][4], bh[4][2], bl[4][2];
#pragma unroll
            for (int mt = 0; mt < 2; ++mt) {
                int abase = (wm * 32 + mt * 16 + (lane >> 2)) * 20 + s * 8 + (lane & 3);
                ah[mt][0] = As_h[abase];            al[mt][0] = As_l[abase];
                ah[mt][1] = As_h[abase + 8 * 20];   al[mt][1] = As_l[abase + 8 * 20];
                ah[mt][2] = As_h[abase + 4];        al[mt][2] = As_l[abase + 4];
                ah[mt][3] = As_h[abase + 8 * 20 + 4]; al[mt][3] = As_l[abase + 8 * 20 + 4];
            }
#pragma unroll
            for (int nt = 0; nt < 4; ++nt) {
                int bbase = (s * 8 + (lane & 3)) * 72 + wn * 32 + nt * 8 + (lane >> 2);
                bh[nt][0] = Bs_h[bbase];          bl[nt][0] = Bs_l[bbase];
                bh[nt][1] = Bs_h[bbase + 4 * 72]; bl[nt][1] = Bs_l[bbase + 4 * 72];
            }
#pragma unroll
            for (int mt = 0; mt < 2; ++mt)
#pragma unroll
                for (int nt = 0; nt < 4; ++nt) {
                    mma_tf32(acc[mt][nt], al[mt], bh[nt]);   // lo*hi
                    mma_tf32(acc[mt][nt], ah[mt], bl[nt]);   // hi*lo
                    mma_tf32(acc[mt][nt], ah[mt], bh[nt]);   // hi*hi
                }
        }
        __syncthreads();
    }

    // epilogue: bias + store (quad-contiguous float2 -> sector-coalesced)
#pragma unroll
    for (int mt = 0; mt < 2; ++mt) {
        int row0 = m0 + wm * 32 + mt * 16 + (lane >> 2);
#pragma unroll
        for (int nt = 0; nt < 4; ++nt) {
            int col = n0 + wn * 32 + nt * 8 + 2 * (lane & 3);
            float b0 = bias[col], b1 = bias[col + 1];
#pragma unroll
            for (int hrow = 0; hrow < 2; ++hrow) {
                size_t mm = (size_t)(row0 + hrow * 8);
                size_t orow = PERM ? ((mm & (TT - 1)) * (size_t)BATCH + (mm >> 8)) : mm;
                float2 o;
                o.x = acc[mt][nt][hrow * 2 + 0] + b0;
                o.y = acc[mt][nt][hrow * 2 + 1] + b1;
                *(float2*)(C + orow * (size_t)GG + col) = o;
            }
        }
    }
}

// ---------------------------------------------------------------------------
// Persistent LSTM layer kernel — VERBATIM from R2 (proven fastest).
// Grid = 256 blocks (16 batch x 16 h chunks), 256 threads. Block owns 64
// batch rows x 16 hidden cols (all 4 gates); c in registers; U slice in SMEM.
// ---------------------------------------------------------------------------
__global__ __launch_bounds__(256, 2) void lstm_rec(
    const float* __restrict__ xz,     // [T][B][G]
    const float* __restrict__ U,      // [H][G] row-major
    float* __restrict__ seqout)       // [T][B][H] or nullptr
{
    extern __shared__ __align__(16) float sm[];
    float* Us = sm;                   // 256*64 = 16384 floats
    float* hs = Us + 256 * 64;        // 64 rows x 32 k     = 2048 floats
    float* zs = hs + 64 * 32;         // 64 rows x 68 (pad) = 4352 floats

    const int tid = threadIdx.x;
    const int bi  = blockIdx.x >> 4;  // batch chunk
    const int hj  = blockIdx.x & 15;  // hidden chunk

    // Load U slice: local col c -> global col (c/16)*HH + hj*16 + (c%16)
    for (int idx = tid; idx < 256 * 64; idx += 256) {
        int k = idx >> 6, c = idx & 63;
        int gcol = (c >> 4) * HH + hj * 16 + (c & 15);
        Us[idx] = U[(size_t)k * GG + gcol];
    }

    // Zero this block's portion of h-state buffer 0 (read at t=0)
    {
        int r = tid >> 2, h0 = (tid & 3) * 4;
#pragma unroll
        for (int p = 0; p < 4; ++p)
            g_hbuf[0][(size_t)(bi * 64 + r) * HH + hj * 16 + h0 + p] = 0.0f;
    }
    gbar();

    const int rx = tid & 15;                    // GEMM col group
    const int ry = tid >> 4;                    // GEMM row group
    const int gcol0 = (rx >> 2) * HH + hj * 16 + (rx & 3) * 4;
    const int er  = tid >> 2;                   // elementwise row 0..63
    const int eh0 = (tid & 3) * 4;              // elementwise h offset

    float creg[4] = {0.0f, 0.0f, 0.0f, 0.0f};   // cell state, registers

    for (int t = 0; t < TT; ++t) {
        const float* hin  = g_hbuf[t & 1];
        float*       hout = g_hbuf[(t + 1) & 1];

        float acc[4][4];
#pragma unroll
        for (int i = 0; i < 4; ++i)
#pragma unroll
            for (int j = 0; j < 4; ++j) acc[i][j] = 0.0f;

        // z = h @ Uslice   (64x64 tile, K=256 in chunks of 32)
        for (int k0 = 0; k0 < HH; k0 += 32) {
            __syncthreads();
#pragma unroll
            for (int q = 0; q < 2; ++q) {
                int f4 = tid * 2 + q;
                int r  = f4 >> 3;
                int c4 = (f4 & 7) * 4;
                *(float4*)(hs + r * 32 + c4) =
                    *(const float4*)(hin + (size_t)(bi * 64 + r) * HH + k0 + c4);
            }
            __syncthreads();
#pragma unroll
            for (int kk = 0; kk < 32; ++kk) {
                float4 b4 = *(const float4*)(Us + (k0 + kk) * 64 + rx * 4);
#pragma unroll
                for (int i = 0; i < 4; ++i) {
                    float a = hs[(ry * 4 + i) * 32 + kk];
                    acc[i][0] = fmaf(a, b4.x, acc[i][0]);
                    acc[i][1] = fmaf(a, b4.y, acc[i][1]);
                    acc[i][2] = fmaf(a, b4.z, acc[i][2]);
                    acc[i][3] = fmaf(a, b4.w, acc[i][3]);
                }
            }
        }
        __syncthreads();

        // z += xz[t], exchange through SMEM so each thread sees all 4 gates
#pragma unroll
        for (int i = 0; i < 4; ++i) {
            int r  = ry * 4 + i;
            int bg = bi * 64 + r;
            float4 xv = *(const float4*)(xz + ((size_t)t * BATCH + bg) * GG + gcol0);
            float4 zv;
            zv.x = acc[i][0] + xv.x;
            zv.y = acc[i][1] + xv.y;
            zv.z = acc[i][2] + xv.z;
            zv.w = acc[i][3] + xv.w;
            *(float4*)(zs + r * 68 + rx * 4) = zv;
        }
        __syncthreads();

        // Gate nonlinearities + state update (gate order i,f,g,o)
#pragma unroll
        for (int p = 0; p < 4; ++p) {
            int ho = eh0 + p;
            float zi = zs[er * 68 +      ho];
            float zf = zs[er * 68 + 16 + ho];
            float zg = zs[er * 68 + 32 + ho];
            float zo = zs[er * 68 + 48 + ho];
            float cc = sigf(zf) * creg[p] + sigf(zi) * tanhf(zg);
            creg[p]  = cc;
            float hh = sigf(zo) * tanhf(cc);
            int bg  = bi * 64 + er;
            int col = hj * 16 + ho;
            hout[(size_t)bg * HH + col] = hh;
            if (seqout) seqout[((size_t)t * BATCH + bg) * HH + col] = hh;
        }
        gbar();   // publish h for next step
    }
    // final h (t=255) lives in g_hbuf[0]
}

// ---------------------------------------------------------------------------
// Head: logits -> softmax -> capped-simplex water-filling (verbatim R2).
// ---------------------------------------------------------------------------
__device__ __forceinline__ float clip01(float x) {
    return fminf(fmaxf(x, 0.0f), 0.1f);
}
__device__ __forceinline__ float wsum(float v) {
#pragma unroll
    for (int o = 16; o > 0; o >>= 1) v += __shfl_xor_sync(0xffffffffu, v, o);
    return v;
}
__device__ __forceinline__ float wmax(float v) {
#pragma unroll
    for (int o = 16; o > 0; o >>= 1) v = fmaxf(v, __shfl_xor_sync(0xffffffffu, v, o));
    return v;
}

__global__ __launch_bounds__(64) void head_kernel(
    const float* __restrict__ Wout, const float* __restrict__ bout,
    float* __restrict__ out)
{
    __shared__ float hsh[HH];
    __shared__ float lg[OO];
    const int b = blockIdx.x;
    const int tid = threadIdx.x;

    for (int i = tid; i < HH; i += 64) hsh[i] = g_hbuf[0][(size_t)b * HH + i];
    __syncthreads();

    if (tid < OO) {
        float a = bout[tid];
        for (int k = 0; k < HH; ++k) a = fmaf(hsh[k], Wout[(size_t)k * OO + tid], a);
        lg[tid] = a;
    }
    __syncthreads();

    if (tid < 32) {
        const bool has1 = (tid + 32) < OO;
        float v0 = lg[tid];
        float v1 = has1 ? lg[tid + 32] : -INFINITY;

        float m  = wmax(fmaxf(v0, v1));
        float e0 = expf(v0 - m);
        float e1 = has1 ? expf(v1 - m) : 0.0f;
        float s  = wsum(e0 + e1);
        float w0 = e0 / s, w1 = e1 / s;

        float old0 = w0, old1 = w1;
        float wc0 = clip01(w0), wc1 = clip01(w1);
        bool done = false;

        for (int it = 0; it < 50; ++it) {
            float leftover = wsum((old0 - wc0) + (old1 - wc1));
            bool m0 = (wc0 != 0.1f), m1 = (wc1 != 0.1f);
            float n0 = m0 ? wc0 : 0.0f;
            float n1 = m1 ? wc1 : 0.0f;
            float denom = wsum(n0 + n1);
            float dd = (denom == 0.0f) ? 1.0f : denom;
            float wn0 = m0 ? wc0 + leftover * n0 / dd : wc0;
            float wn1 = m1 ? wc1 + leftover * n1 / dd : wc1;
            bool over = __any_sync(0xffffffffu, (wn0 > 0.1f) || (wn1 > 0.1f));
            bool ndone = !over;
            float wx0 = ndone ? wn0 : clip01(wn0);
            float wx1 = ndone ? wn1 : clip01(wn1);
            if (!done) { old0 = wn0; old1 = wn1; wc0 = wx0; wc1 = wx1; }
            done = done || ndone;
        }

        out[(size_t)b * OO + tid] = wc0;
        if (has1) out[(size_t)b * OO + tid + 32] = wc1;
    }
}

// ---------------------------------------------------------------------------
// Launch (graph-capturable: kernel launches only)
// ---------------------------------------------------------------------------
extern "C" void kernel_launch(void* const* d_in, const int* in_sizes, int n_in,
                              void* d_out, int out_size)
{
    const float* x    = (const float*)d_in[0];
    const float* W0   = (const float*)d_in[1];
    const float* U0   = (const float*)d_in[2];
    const float* b0   = (const float*)d_in[3];
    const float* W1   = (const float*)d_in[4];
    const float* U1   = (const float*)d_in[5];
    const float* b1   = (const float*)d_in[6];
    const float* Wout = (const float*)d_in[7];
    const float* bout = (const float*)d_in[8];
    float* out = (float*)d_out;

    float *p_xz = nullptr, *p_h0 = nullptr;
    cudaGetSymbolAddress((void**)&p_xz, g_xz);
    cudaGetSymbolAddress((void**)&p_h0, g_h0seq);

    const int REC_SMEM = (256 * 64 + 64 * 32 + 64 * 68) * (int)sizeof(float); // 91136
    cudaFuncSetAttribute(lstm_rec, cudaFuncAttributeMaxDynamicSharedMemorySize, REC_SMEM);

    dim3 gg(16, (BATCH * TT) / 128);   // (16, 2048)

    // Layer 0 input projection: xz0[t][b][g]  (split-tf32 tensor cores)
    gemm_tf32<true><<<gg, 256>>>(x, W0, b0, p_xz, FF);
    // Layer 0 recurrence -> h0seq[t][b][h]
    lstm_rec<<<256, 256, REC_SMEM>>>(p_xz, U0, p_h0);
    // Layer 1 input projection (reuses g_xz)
    gemm_tf32<false><<<gg, 256>>>(p_h0, W1, b1, p_xz, HH);
    // Layer 1 recurrence (final h ends in g_hbuf[0])
    lstm_rec<<<256, 256, REC_SMEM>>>(p_xz, U1, nullptr);
    // Head: logits -> softmax -> rebalance
    head_kernel<<<BATCH, 64>>>(Wout, bout, out);
}

// round 8
// speedup vs baseline: 2.1001x; 1.5085x over previous
#include <cuda_runtime.h>
#include <cuda_fp16.h>
#include <math.h>
#include <stdint.h>

// Problem constants
#define BATCH 1024
#define TT    256
#define FF    128
#define HH    256
#define GG    1024   // 4*H
#define OO    50

// ---------------------------------------------------------------------------
// Static device scratch (allocation-free per harness rules)
// ---------------------------------------------------------------------------
__device__ float g_xz[(size_t)TT * BATCH * GG];    // [t][b][g] fp32
__device__ __half g_h0h[(size_t)TT * BATCH * HH];  // layer-0 h seq, hi
__device__ __half g_h0l[(size_t)TT * BATCH * HH];  // layer-0 h seq, lo
__device__ __half g_hbh[2][BATCH * HH];            // h state hi, dbl-buf
__device__ __half g_hbl[2][BATCH * HH];            // h state lo
__device__ unsigned g_barleaf[16 * 32];            // leaf counters, 128B apart
__device__ unsigned g_barroot = 0;
__device__ unsigned g_bargen = 0;

// ---------------------------------------------------------------------------
// Two-level grid barrier: 256 blocks = 16 leaves x 16. Arrival contention
// 16-way per counter (~500 cyc) instead of 256-way (~7000 cyc).
// ---------------------------------------------------------------------------
__device__ __forceinline__ void gbar() {
    __syncthreads();
    if (threadIdx.x == 0) {
        __threadfence();
        unsigned gen = *((volatile unsigned*)&g_bargen);
        unsigned* leaf = &g_barleaf[(blockIdx.x & 15) * 32];
        if (atomicAdd(leaf, 1) == 15) {
            atomicExch(leaf, 0);                       // all 16 arrived; safe
            if (atomicAdd(&g_barroot, 1) == 15) {
                atomicExch(&g_barroot, 0);
                __threadfence();
                atomicExch(&g_bargen, gen + 1);
            } else {
                while (*((volatile unsigned*)&g_bargen) == gen) { __nanosleep(16); }
            }
        } else {
            while (*((volatile unsigned*)&g_bargen) == gen) { __nanosleep(16); }
        }
        __threadfence();
    }
    __syncthreads();
}

__device__ __forceinline__ float sigf(float x) { return 1.0f / (1.0f + expf(-x)); }

// ---------------------------------------------------------------------------
// fp16 mma.sync m16n8k16, f32 accumulate
// ---------------------------------------------------------------------------
__device__ __forceinline__ void mma_f16(float* c, const unsigned* a, const unsigned* b) {
    asm volatile(
        "mma.sync.aligned.m16n8k16.row.col.f32.f16.f16.f32 "
        "{%0,%1,%2,%3}, {%4,%5,%6,%7}, {%8,%9}, {%0,%1,%2,%3};"
        : "+f"(c[0]), "+f"(c[1]), "+f"(c[2]), "+f"(c[3])
        : "r"(a[0]), "r"(a[1]), "r"(a[2]), "r"(a[3]), "r"(b[0]), "r"(b[1]));
}

// split fp32 -> fp16 hi + fp16 lo (hi+lo carries ~22 significand bits)
__device__ __forceinline__ void splith(float f, __half& h, __half& l) {
    h = __float2half_rn(f);
    l = __float2half_rn(f - __half2float(h));
}
// pack two fp32 into half2 hi/lo u32 words
__device__ __forceinline__ void split2(float a, float b, unsigned& h, unsigned& l) {
    __half2 h2 = __floats2half2_rn(a, b);
    float ra = a - __low2float(h2);
    float rb = b - __high2float(h2);
    __half2 l2 = __floats2half2_rn(ra, rb);
    h = *(unsigned*)&h2;
    l = *(unsigned*)&l2;
}

// ---------------------------------------------------------------------------
// GEMM + bias: C[M,1024] = A[M,K] @ W[K,1024] + bias   (fp16 3-term split mma)
// Block 128x64, BK=32, 256 thr = 8 warps (4M x 2N), warp 32x32 (mt2 x nt4).
// PERM: output rows m=b*T+t -> t*B+b.  PRESPLIT: A given as fp16 hi/lo planes.
// ---------------------------------------------------------------------------
template<bool PERM, bool PRESPLIT>
__global__ __launch_bounds__(256) void gemm_f16(
    const float* __restrict__ A32,
    const __half* __restrict__ Agh, const __half* __restrict__ Agl,
    const float* __restrict__ W, const float* __restrict__ bias,
    float* __restrict__ C, int K)
{
    __shared__ __align__(16) unsigned Ah32[128 * 20];
    __shared__ __align__(16) unsigned Al32[128 * 20];
    __shared__ __align__(16) unsigned Bh32[64 * 20];
    __shared__ __align__(16) unsigned Bl32[64 * 20];
    __half* BhB = (__half*)Bh32;
    __half* BlB = (__half*)Bl32;

    const int tid  = threadIdx.x;
    const int lane = tid & 31;
    const int w    = tid >> 5;
    const int wm   = w & 3, wn = w >> 2;
    const int trow = lane >> 2, q = lane & 3;
    const int m0   = blockIdx.y * 128;
    const int n0   = blockIdx.x * 64;

    const int arow = tid >> 1;          // 0..127
    const int akb  = (tid & 1) * 16;    // k offset (half elems)
    const int bk   = tid >> 3;          // 0..31 (k row)
    const int bnb  = (tid & 7) * 8;     // n offset

    float acc[2][4][4];
#pragma unroll
    for (int i = 0; i < 2; ++i)
#pragma unroll
        for (int j = 0; j < 4; ++j)
#pragma unroll
            for (int r = 0; r < 4; ++r) acc[i][j][r] = 0.0f;

    const int iters = K >> 5;

    // register prefetch of tile 0
    uint4 pah, pah2, pal, pal2;
    float4 par[4];
    float4 pbr0, pbr1;
    if (PRESPLIT) {
        const __half* ap = Agh + (size_t)(m0 + arow) * K + akb;
        const __half* lp = Agl + (size_t)(m0 + arow) * K + akb;
        pah = *(const uint4*)ap; pah2 = *(const uint4*)(ap + 8);
        pal = *(const uint4*)lp; pal2 = *(const uint4*)(lp + 8);
    } else {
        const float* ap = A32 + (size_t)(m0 + arow) * K + akb;
#pragma unroll
        for (int i = 0; i < 4; ++i) par[i] = *(const float4*)(ap + i * 4);
    }
    pbr0 = *(const float4*)(W + (size_t)bk * GG + n0 + bnb);
    pbr1 = *(const float4*)(W + (size_t)bk * GG + n0 + bnb + 4);

    for (int it = 0; it < iters; ++it) {
        // ---- STS staged tile
        if (PRESPLIT) {
            *(uint4*)&Ah32[arow * 20 + (akb >> 1)]     = pah;
            *(uint4*)&Ah32[arow * 20 + (akb >> 1) + 4] = pah2;
            *(uint4*)&Al32[arow * 20 + (akb >> 1)]     = pal;
            *(uint4*)&Al32[arow * 20 + (akb >> 1) + 4] = pal2;
        } else {
            float f[16];
#pragma unroll
            for (int i = 0; i < 4; ++i) {
                f[i*4+0] = par[i].x; f[i*4+1] = par[i].y;
                f[i*4+2] = par[i].z; f[i*4+3] = par[i].w;
            }
            unsigned h[8], l[8];
#pragma unroll
            for (int j = 0; j < 8; ++j) split2(f[2*j], f[2*j+1], h[j], l[j]);
            *(uint4*)&Ah32[arow * 20 + (akb >> 1)]     = make_uint4(h[0], h[1], h[2], h[3]);
            *(uint4*)&Ah32[arow * 20 + (akb >> 1) + 4] = make_uint4(h[4], h[5], h[6], h[7]);
            *(uint4*)&Al32[arow * 20 + (akb >> 1)]     = make_uint4(l[0], l[1], l[2], l[3]);
            *(uint4*)&Al32[arow * 20 + (akb >> 1) + 4] = make_uint4(l[4], l[5], l[6], l[7]);
        }
        {
            float f[8] = {pbr0.x, pbr0.y, pbr0.z, pbr0.w, pbr1.x, pbr1.y, pbr1.z, pbr1.w};
#pragma unroll
            for (int j = 0; j < 8; ++j) {
                __half hb, lb;
                splith(f[j], hb, lb);
                BhB[(bnb + j) * 40 + bk] = hb;
                BlB[(bnb + j) * 40 + bk] = lb;
            }
        }
        __syncthreads();

        // ---- prefetch next tile into registers
        if (it + 1 < iters) {
            int kg = (it + 1) * 32;
            if (PRESPLIT) {
                const __half* ap = Agh + (size_t)(m0 + arow) * K + kg + akb;
                const __half* lp = Agl + (size_t)(m0 + arow) * K + kg + akb;
                pah = *(const uint4*)ap; pah2 = *(const uint4*)(ap + 8);
                pal = *(const uint4*)lp; pal2 = *(const uint4*)(lp + 8);
            } else {
                const float* ap = A32 + (size_t)(m0 + arow) * K + kg + akb;
#pragma unroll
                for (int i = 0; i < 4; ++i) par[i] = *(const float4*)(ap + i * 4);
            }
            pbr0 = *(const float4*)(W + (size_t)(kg + bk) * GG + n0 + bnb);
            pbr1 = *(const float4*)(W + (size_t)(kg + bk) * GG + n0 + bnb + 4);
        }

        // ---- mma: 2 k16 steps
#pragma unroll
        for (int s = 0; s < 2; ++s) {
            unsigned ah[2][4], al[2][4];
#pragma unroll
            for (int mt = 0; mt < 2; ++mt) {
                int ab = (wm * 32 + mt * 16 + trow) * 20 + s * 8 + q;
                ah[mt][0] = Ah32[ab];       ah[mt][1] = Ah32[ab + 160];
                ah[mt][2] = Ah32[ab + 4];   ah[mt][3] = Ah32[ab + 164];
                al[mt][0] = Al32[ab];       al[mt][1] = Al32[ab + 160];
                al[mt][2] = Al32[ab + 4];   al[mt][3] = Al32[ab + 164];
            }
#pragma unroll
            for (int nt = 0; nt < 4; ++nt) {
                int bb = (wn * 32 + nt * 8 + trow) * 20 + s * 8 + q;
                unsigned bh[2] = {Bh32[bb], Bh32[bb + 4]};
                unsigned bl[2] = {Bl32[bb], Bl32[bb + 4]};
#pragma unroll
                for (int mt = 0; mt < 2; ++mt) {
                    mma_f16(acc[mt][nt], ah[mt], bh);
                    mma_f16(acc[mt][nt], ah[mt], bl);
                    mma_f16(acc[mt][nt], al[mt], bh);
                }
            }
        }
        __syncthreads();
    }

    // ---- epilogue
#pragma unroll
    for (int mt = 0; mt < 2; ++mt) {
        int row0 = m0 + wm * 32 + mt * 16 + trow;
#pragma unroll
        for (int nt = 0; nt < 4; ++nt) {
            int col = n0 + wn * 32 + nt * 8 + 2 * q;
            float b0 = bias[col], b1 = bias[col + 1];
#pragma unroll
            for (int hr = 0; hr < 2; ++hr) {
                size_t mm = (size_t)(row0 + hr * 8);
                size_t orow = PERM ? ((mm & (TT - 1)) * (size_t)BATCH + (mm >> 8)) : mm;
                float2 o;
                o.x = acc[mt][nt][hr * 2 + 0] + b0;
                o.y = acc[mt][nt][hr * 2 + 1] + b1;
                *(float2*)(C + orow * (size_t)GG + col) = o;
            }
        }
    }
}

// ---------------------------------------------------------------------------
// Persistent LSTM layer, fp16 split mma. 256 blocks (16 batch x 16 h chunks),
// 256 thr = 8 warps (4M x 2N); block tile 64 rows x 64 gate-cols.
// U pre-split in SMEM (gate-permuted cols: local col = 8*gate + h'), h state
// pre-split in global fp16 planes. Cell update fully register-resident.
// ---------------------------------------------------------------------------
__global__ __launch_bounds__(256, 2) void lstm_rec_tc(
    const float* __restrict__ xz,      // [T][B][G] fp32
    const float* __restrict__ U,       // [H][G] fp32
    __half* __restrict__ seqH,         // [T][B][H] or null
    __half* __restrict__ seqL)
{
    extern __shared__ __align__(16) unsigned smw[];
    unsigned* Uh32 = smw;                  // 64 x 132 words
    unsigned* Ul32 = smw + 8448;
    unsigned* HhB[2] = {smw + 16896, smw + 19456};   // 64 x 20 words each
    unsigned* HlB[2] = {smw + 18176, smw + 20736};
    __half* UhE = (__half*)Uh32;
    __half* UlE = (__half*)Ul32;

    const int tid  = threadIdx.x;
    const int lane = tid & 31;
    const int w    = tid >> 5;
    const int wm   = w & 3, wn = w >> 2;
    const int trow = lane >> 2, q = lane & 3;
    const int bi   = blockIdx.x >> 4;
    const int hj   = blockIdx.x & 15;

    // ---- load + split U slice, gate-permuted: n_local -> (wn, gate, h')
    for (int idx = tid; idx < 64 * 256; idx += 256) {
        int n = idx & 63, k = idx >> 6;
        int gcol = ((n >> 3) & 3) * HH + hj * 16 + (n >> 5) * 8 + (n & 7);
        float v = U[(size_t)k * GG + gcol];
        __half hb, lb;
        splith(v, hb, lb);
        UhE[n * 264 + k] = hb;
        UlE[n * 264 + k] = lb;
    }
    // ---- zero h-state buffer 0 (this block's cols)
    {
        int r = tid >> 2, c0 = (tid & 3) * 4;
        uint2 z = make_uint2(0u, 0u);
        *(uint2*)&g_hbh[0][(size_t)(bi * 64 + r) * HH + hj * 16 + c0] = z;
        *(uint2*)&g_hbl[0][(size_t)(bi * 64 + r) * HH + hj * 16 + c0] = z;
    }
    gbar();

    const int arow0 = (wm * 16 + trow) * 20;
    const int hcol0 = hj * 16 + wn * 8 + 2 * q;
    const int srow  = tid >> 2;            // staging row 0..63
    const int skw   = (tid & 3) * 4;       // staging k offset (u32 words)

    float cst[4] = {0.f, 0.f, 0.f, 0.f};   // cell state [rr*2+pp]

    for (int t = 0; t < TT; ++t) {
        const __half* hinH = g_hbh[t & 1];
        const __half* hinL = g_hbl[t & 1];
        __half* houtH = g_hbh[(t + 1) & 1];
        __half* houtL = g_hbl[(t + 1) & 1];

        // xz prefetch (gate-scattered, h-pair contiguous)
        float2 xv[2][4];
#pragma unroll
        for (int rr = 0; rr < 2; ++rr) {
            int bgr = bi * 64 + wm * 16 + trow + rr * 8;
            const float* xp = xz + ((size_t)t * BATCH + bgr) * GG + hcol0;
#pragma unroll
            for (int g = 0; g < 4; ++g) xv[rr][g] = *(const float2*)(xp + g * 256);
        }

        // preload h chunk 0
        const __half* hrowH = hinH + (size_t)(bi * 64 + srow) * HH;
        const __half* hrowL = hinL + (size_t)(bi * 64 + srow) * HH;
        uint4 ph = *(const uint4*)(hrowH + skw * 2);
        uint4 pl = *(const uint4*)(hrowL + skw * 2);

        float acc[4][4];
#pragma unroll
        for (int g = 0; g < 4; ++g)
#pragma unroll
            for (int r = 0; r < 4; ++r) acc[g][r] = 0.0f;

        for (int c = 0; c < 8; ++c) {
            const int cb = c & 1;
            *(uint4*)&HhB[cb][srow * 20 + skw] = ph;
            *(uint4*)&HlB[cb][srow * 20 + skw] = pl;
            __syncthreads();
            if (c < 7) {
                ph = *(const uint4*)(hrowH + (c + 1) * 32 + skw * 2);
                pl = *(const uint4*)(hrowL + (c + 1) * 32 + skw * 2);
            }
            const unsigned* HHc = HhB[cb];
            const unsigned* HLc = HlB[cb];
#pragma unroll
            for (int s = 0; s < 2; ++s) {
                int ab = arow0 + s * 8 + q;
                unsigned ah[4] = {HHc[ab], HHc[ab + 160], HHc[ab + 4], HHc[ab + 164]};
                unsigned al[4] = {HLc[ab], HLc[ab + 160], HLc[ab + 4], HLc[ab + 164]};
                int kofs = c * 16 + s * 8 + q;
#pragma unroll
                for (int g = 0; g < 4; ++g) {
                    int nb = (wn * 32 + g * 8 + trow) * 132 + kofs;
                    unsigned bh[2] = {Uh32[nb], Uh32[nb + 4]};
                    unsigned bl[2] = {Ul32[nb], Ul32[nb + 4]};
                    mma_f16(acc[g], ah, bh);
                    mma_f16(acc[g], ah, bl);
                    mma_f16(acc[g], al, bh);
                }
            }
            __syncthreads();
        }

        // epilogue: all four gates of (row, h-pair) live in this lane's regs
#pragma unroll
        for (int rr = 0; rr < 2; ++rr) {
            int bgr = bi * 64 + wm * 16 + trow + rr * 8;
            float hv[2];
#pragma unroll
            for (int pp = 0; pp < 2; ++pp) {
                int a = rr * 2 + pp;
                float zi = acc[0][a] + (pp ? xv[rr][0].y : xv[rr][0].x);
                float zf = acc[1][a] + (pp ? xv[rr][1].y : xv[rr][1].x);
                float zg = acc[2][a] + (pp ? xv[rr][2].y : xv[rr][2].x);
                float zo = acc[3][a] + (pp ? xv[rr][3].y : xv[rr][3].x);
                float cc = sigf(zf) * cst[a] + sigf(zi) * tanhf(zg);
                cst[a] = cc;
                hv[pp] = sigf(zo) * tanhf(cc);
            }
            __half h0h, h0l, h1h, h1l;
            splith(hv[0], h0h, h0l);
            splith(hv[1], h1h, h1l);
            __half2 ph2; ph2.x = h0h; ph2.y = h1h;
            __half2 pl2; pl2.x = h0l; pl2.y = h1l;
            size_t o = (size_t)bgr * HH + hcol0;
            *(__half2*)&houtH[o] = ph2;
            *(__half2*)&houtL[o] = pl2;
            if (seqH) {
                size_t so = ((size_t)t * BATCH + bgr) * HH + hcol0;
                *(__half2*)&seqH[so] = ph2;
                *(__half2*)&seqL[so] = pl2;
            }
        }
        gbar();   // publish h for next step
    }
    // final h in g_hbh/g_hbl[0]
}

// ---------------------------------------------------------------------------
// Head: reconstruct h = hi+lo; logits -> softmax -> water-filling (R2 logic).
// ---------------------------------------------------------------------------
__device__ __forceinline__ float clip01(float x) {
    return fminf(fmaxf(x, 0.0f), 0.1f);
}
__device__ __forceinline__ float wsum(float v) {
#pragma unroll
    for (int o = 16; o > 0; o >>= 1) v += __shfl_xor_sync(0xffffffffu, v, o);
    return v;
}
__device__ __forceinline__ float wmax(float v) {
#pragma unroll
    for (int o = 16; o > 0; o >>= 1) v = fmaxf(v, __shfl_xor_sync(0xffffffffu, v, o));
    return v;
}

__global__ __launch_bounds__(64) void head_kernel(
    const float* __restrict__ Wout, const float* __restrict__ bout,
    float* __restrict__ out)
{
    __shared__ float hsh[HH];
    __shared__ float lg[OO];
    const int b = blockIdx.x;
    const int tid = threadIdx.x;

    for (int i = tid; i < HH; i += 64)
        hsh[i] = __half2float(g_hbh[0][(size_t)b * HH + i])
               + __half2float(g_hbl[0][(size_t)b * HH + i]);
    __syncthreads();

    if (tid < OO) {
        float a = bout[tid];
        for (int k = 0; k < HH; ++k) a = fmaf(hsh[k], Wout[(size_t)k * OO + tid], a);
        lg[tid] = a;
    }
    __syncthreads();

    if (tid < 32) {
        const bool has1 = (tid + 32) < OO;
        float v0 = lg[tid];
        float v1 = has1 ? lg[tid + 32] : -INFINITY;

        float m  = wmax(fmaxf(v0, v1));
        float e0 = expf(v0 - m);
        float e1 = has1 ? expf(v1 - m) : 0.0f;
        float s  = wsum(e0 + e1);
        float w0 = e0 / s, w1 = e1 / s;

        float old0 = w0, old1 = w1;
        float wc0 = clip01(w0), wc1 = clip01(w1);
        bool done = false;

        for (int it = 0; it < 50; ++it) {
            float leftover = wsum((old0 - wc0) + (old1 - wc1));
            bool m0 = (wc0 != 0.1f), m1 = (wc1 != 0.1f);
            float n0 = m0 ? wc0 : 0.0f;
            float n1 = m1 ? wc1 : 0.0f;
            float denom = wsum(n0 + n1);
            float dd = (denom == 0.0f) ? 1.0f : denom;
            float wn0 = m0 ? wc0 + leftover * n0 / dd : wc0;
            float wn1 = m1 ? wc1 + leftover * n1 / dd : wc1;
            bool over = __any_sync(0xffffffffu, (wn0 > 0.1f) || (wn1 > 0.1f));
            bool ndone = !over;
            float wx0 = ndone ? wn0 : clip01(wn0);
            float wx1 = ndone ? wn1 : clip01(wn1);
            if (!done) { old0 = wn0; old1 = wn1; wc0 = wx0; wc1 = wx1; }
            done = done || ndone;
        }

        out[(size_t)b * OO + tid] = wc0;
        if (has1) out[(size_t)b * OO + tid + 32] = wc1;
    }
}

// ---------------------------------------------------------------------------
// Launch (graph-capturable: kernel launches only)
// ---------------------------------------------------------------------------
extern "C" void kernel_launch(void* const* d_in, const int* in_sizes, int n_in,
                              void* d_out, int out_size)
{
    const float* x    = (const float*)d_in[0];
    const float* W0   = (const float*)d_in[1];
    const float* U0   = (const float*)d_in[2];
    const float* b0   = (const float*)d_in[3];
    const float* W1   = (const float*)d_in[4];
    const float* U1   = (const float*)d_in[5];
    const float* b1   = (const float*)d_in[6];
    const float* Wout = (const float*)d_in[7];
    const float* bout = (const float*)d_in[8];
    float* out = (float*)d_out;

    float* p_xz = nullptr;
    __half *p_h0h = nullptr, *p_h0l = nullptr;
    cudaGetSymbolAddress((void**)&p_xz,  g_xz);
    cudaGetSymbolAddress((void**)&p_h0h, g_h0h);
    cudaGetSymbolAddress((void**)&p_h0l, g_h0l);

    const int REC_SMEM = 88064;   // U hi/lo (67584) + h chunk dbl-buf (20480)
    cudaFuncSetAttribute(lstm_rec_tc, cudaFuncAttributeMaxDynamicSharedMemorySize, REC_SMEM);

    dim3 gg(GG / 64, (BATCH * TT) / 128);   // (16, 2048)

    // Layer 0 input projection: xz0[t][b][g]
    gemm_f16<true, false><<<gg, 256>>>(x, nullptr, nullptr, W0, b0, p_xz, FF);
    // Layer 0 recurrence -> pre-split h0seq planes
    lstm_rec_tc<<<256, 256, REC_SMEM>>>(p_xz, U0, p_h0h, p_h0l);
    // Layer 1 input projection (A pre-split, reuses g_xz)
    gemm_f16<false, true><<<gg, 256>>>(nullptr, p_h0h, p_h0l, W1, b1, p_xz, HH);
    // Layer 1 recurrence (final h ends in g_hbh/g_hbl[0])
    lstm_rec_tc<<<256, 256, REC_SMEM>>>(p_xz, U1, nullptr, nullptr);
    // Head: logits -> softmax -> rebalance
    head_kernel<<<BATCH, 64>>>(Wout, bout, out);
}

// round 9
// speedup vs baseline: 2.2419x; 1.0676x over previous
#include <cuda_runtime.h>
#include <cuda_fp16.h>
#include <math.h>
#include <stdint.h>

// Problem constants
#define BATCH 1024
#define TT    256
#define FF    128
#define HH    256
#define GG    1024   // 4*H
#define OO    50

// ---------------------------------------------------------------------------
// Static device scratch (allocation-free per harness rules)
// ---------------------------------------------------------------------------
__device__ float g_xz[(size_t)TT * BATCH * GG];    // [t][b][g] fp32
__device__ __half g_h0h[(size_t)TT * BATCH * HH];  // layer-0 h seq, hi
__device__ __half g_h0l[(size_t)TT * BATCH * HH];  // layer-0 h seq, lo
__device__ __half g_hbh[2][BATCH * HH];            // h state hi, dbl-buf
__device__ __half g_hbl[2][BATCH * HH];            // h state lo
__device__ unsigned g_barleaf[16 * 32];            // leaf counters, 128B apart
__device__ unsigned g_barroot = 0;
__device__ unsigned g_bargen = 0;

// ---------------------------------------------------------------------------
// Two-level grid barrier (proven R7): 256 blocks = 16 leaves x 16.
// ---------------------------------------------------------------------------
__device__ __forceinline__ void gbar() {
    __syncthreads();
    if (threadIdx.x == 0) {
        __threadfence();
        unsigned gen = *((volatile unsigned*)&g_bargen);
        unsigned* leaf = &g_barleaf[(blockIdx.x & 15) * 32];
        if (atomicAdd(leaf, 1) == 15) {
            atomicExch(leaf, 0);
            if (atomicAdd(&g_barroot, 1) == 15) {
                atomicExch(&g_barroot, 0);
                __threadfence();
                atomicExch(&g_bargen, gen + 1);
            } else {
                while (*((volatile unsigned*)&g_bargen) == gen) { __nanosleep(16); }
            }
        } else {
            while (*((volatile unsigned*)&g_bargen) == gen) { __nanosleep(16); }
        }
        __threadfence();
    }
    __syncthreads();
}

__device__ __forceinline__ float sigf(float x) { return 1.0f / (1.0f + expf(-x)); }

// ---------------------------------------------------------------------------
// fp16 mma.sync m16n8k16 (f32 accumulate) + ldmatrix helpers
// ---------------------------------------------------------------------------
__device__ __forceinline__ void mma_f16(float* c, const unsigned* a, const unsigned* b) {
    asm volatile(
        "mma.sync.aligned.m16n8k16.row.col.f32.f16.f16.f32 "
        "{%0,%1,%2,%3}, {%4,%5,%6,%7}, {%8,%9}, {%0,%1,%2,%3};"
        : "+f"(c[0]), "+f"(c[1]), "+f"(c[2]), "+f"(c[3])
        : "r"(a[0]), "r"(a[1]), "r"(a[2]), "r"(a[3]), "r"(b[0]), "r"(b[1]));
}
__device__ __forceinline__ void ldsm_x4(unsigned* r, uint32_t addr) {
    asm volatile("ldmatrix.sync.aligned.m8n8.x4.shared.b16 {%0,%1,%2,%3}, [%4];"
        : "=r"(r[0]), "=r"(r[1]), "=r"(r[2]), "=r"(r[3]) : "r"(addr));
}
__device__ __forceinline__ uint32_t smem_u32(const void* p) {
    uint32_t a;
    asm("{ .reg .u64 t; cvta.to.shared.u64 t, %1; cvt.u32.u64 %0, t; }"
        : "=r"(a) : "l"(p));
    return a;
}

// split fp32 -> fp16 hi + fp16 lo (hi+lo carries ~22 significand bits)
__device__ __forceinline__ void splith(float f, __half& h, __half& l) {
    h = __float2half_rn(f);
    l = __float2half_rn(f - __half2float(h));
}
__device__ __forceinline__ void split2(float a, float b, unsigned& h, unsigned& l) {
    __half2 h2 = __floats2half2_rn(a, b);
    float ra = a - __low2float(h2);
    float rb = b - __high2float(h2);
    __half2 l2 = __floats2half2_rn(ra, rb);
    h = *(unsigned*)&h2;
    l = *(unsigned*)&l2;
}

// ---------------------------------------------------------------------------
// GEMM + bias: C[M,1024] = A[M,K] @ W[K,1024] + bias   (fp16 3-term split mma)
// Block 128x64, BK=32, 256 thr = 8 warps (4M x 2N), warp 32x32.
// Fragment loads via ldmatrix.x4 (layout identical to R7 scalar mapping).
// ---------------------------------------------------------------------------
template<bool PERM, bool PRESPLIT>
__global__ __launch_bounds__(256) void gemm_f16(
    const float* __restrict__ A32,
    const __half* __restrict__ Agh, const __half* __restrict__ Agl,
    const float* __restrict__ W, const float* __restrict__ bias,
    float* __restrict__ C, int K)
{
    __shared__ __align__(16) unsigned Ah32[128 * 20];
    __shared__ __align__(16) unsigned Al32[128 * 20];
    __shared__ __align__(16) unsigned Bh32[64 * 20];
    __shared__ __align__(16) unsigned Bl32[64 * 20];
    __half* BhB = (__half*)Bh32;
    __half* BlB = (__half*)Bl32;

    const int tid  = threadIdx.x;
    const int lane = tid & 31;
    const int w    = tid >> 5;
    const int wm   = w & 3, wn = w >> 2;
    const int trow = lane >> 2, q = lane & 3;
    const int m0   = blockIdx.y * 128;
    const int n0   = blockIdx.x * 64;

    const int arow = tid >> 1;
    const int akb  = (tid & 1) * 16;
    const int bk   = tid >> 3;
    const int bnb  = (tid & 7) * 8;

    // ldmatrix byte-offset bases (row strides: A 80B, B 80B)
    const uint32_t smA_h = smem_u32(Ah32);
    const uint32_t smA_l = smem_u32(Al32);
    const uint32_t smB_h = smem_u32(Bh32);
    const uint32_t smB_l = smem_u32(Bl32);
    const uint32_t aofs = (uint32_t)(wm * 32 + (lane & 15)) * 80 + ((lane >> 4) & 1) * 16;
    const uint32_t bofs = (uint32_t)(wn * 32 + ((lane >> 4) & 1) * 8 + (lane & 7)) * 80
                        + ((lane >> 3) & 1) * 16;

    float acc[2][4][4];
#pragma unroll
    for (int i = 0; i < 2; ++i)
#pragma unroll
        for (int j = 0; j < 4; ++j)
#pragma unroll
            for (int r = 0; r < 4; ++r) acc[i][j][r] = 0.0f;

    const int iters = K >> 5;

    uint4 pah, pah2, pal, pal2;
    float4 par[4];
    float4 pbr0, pbr1;
    if (PRESPLIT) {
        const __half* ap = Agh + (size_t)(m0 + arow) * K + akb;
        const __half* lp = Agl + (size_t)(m0 + arow) * K + akb;
        pah = *(const uint4*)ap; pah2 = *(const uint4*)(ap + 8);
        pal = *(const uint4*)lp; pal2 = *(const uint4*)(lp + 8);
    } else {
        const float* ap = A32 + (size_t)(m0 + arow) * K + akb;
#pragma unroll
        for (int i = 0; i < 4; ++i) par[i] = *(const float4*)(ap + i * 4);
    }
    pbr0 = *(const float4*)(W + (size_t)bk * GG + n0 + bnb);
    pbr1 = *(const float4*)(W + (size_t)bk * GG + n0 + bnb + 4);

    for (int it = 0; it < iters; ++it) {
        if (PRESPLIT) {
            *(uint4*)&Ah32[arow * 20 + (akb >> 1)]     = pah;
            *(uint4*)&Ah32[arow * 20 + (akb >> 1) + 4] = pah2;
            *(uint4*)&Al32[arow * 20 + (akb >> 1)]     = pal;
            *(uint4*)&Al32[arow * 20 + (akb >> 1) + 4] = pal2;
        } else {
            float f[16];
#pragma unroll
            for (int i = 0; i < 4; ++i) {
                f[i*4+0] = par[i].x; f[i*4+1] = par[i].y;
                f[i*4+2] = par[i].z; f[i*4+3] = par[i].w;
            }
            unsigned h[8], l[8];
#pragma unroll
            for (int j = 0; j < 8; ++j) split2(f[2*j], f[2*j+1], h[j], l[j]);
            *(uint4*)&Ah32[arow * 20 + (akb >> 1)]     = make_uint4(h[0], h[1], h[2], h[3]);
            *(uint4*)&Ah32[arow * 20 + (akb >> 1) + 4] = make_uint4(h[4], h[5], h[6], h[7]);
            *(uint4*)&Al32[arow * 20 + (akb >> 1)]     = make_uint4(l[0], l[1], l[2], l[3]);
            *(uint4*)&Al32[arow * 20 + (akb >> 1) + 4] = make_uint4(l[4], l[5], l[6], l[7]);
        }
        {
            float f[8] = {pbr0.x, pbr0.y, pbr0.z, pbr0.w, pbr1.x, pbr1.y, pbr1.z, pbr1.w};
#pragma unroll
            for (int j = 0; j < 8; ++j) {
                __half hb, lb;
                splith(f[j], hb, lb);
                BhB[(bnb + j) * 40 + bk] = hb;
                BlB[(bnb + j) * 40 + bk] = lb;
            }
        }
        __syncthreads();

        if (it + 1 < iters) {
            int kg = (it + 1) * 32;
            if (PRESPLIT) {
                const __half* ap = Agh + (size_t)(m0 + arow) * K + kg + akb;
                const __half* lp = Agl + (size_t)(m0 + arow) * K + kg + akb;
                pah = *(const uint4*)ap; pah2 = *(const uint4*)(ap + 8);
                pal = *(const uint4*)lp; pal2 = *(const uint4*)(lp + 8);
            } else {
                const float* ap = A32 + (size_t)(m0 + arow) * K + kg + akb;
#pragma unroll
                for (int i = 0; i < 4; ++i) par[i] = *(const float4*)(ap + i * 4);
            }
            pbr0 = *(const float4*)(W + (size_t)(kg + bk) * GG + n0 + bnb);
            pbr1 = *(const float4*)(W + (size_t)(kg + bk) * GG + n0 + bnb + 4);
        }

#pragma unroll
        for (int s = 0; s < 2; ++s) {
            unsigned ah[2][4], al[2][4], bh[2][4], bl[2][4];
#pragma unroll
            for (int mt = 0; mt < 2; ++mt) {
                ldsm_x4(ah[mt], smA_h + aofs + mt * 1280 + s * 32);
                ldsm_x4(al[mt], smA_l + aofs + mt * 1280 + s * 32);
            }
#pragma unroll
            for (int np = 0; np < 2; ++np) {
                ldsm_x4(bh[np], smB_h + bofs + np * 1280 + s * 32);
                ldsm_x4(bl[np], smB_l + bofs + np * 1280 + s * 32);
            }
#pragma unroll
            for (int np = 0; np < 2; ++np)
#pragma unroll
                for (int half = 0; half < 2; ++half) {
                    int nt = np * 2 + half;
#pragma unroll
                    for (int mt = 0; mt < 2; ++mt) {
                        mma_f16(acc[mt][nt], ah[mt], bh[np] + half * 2);
                        mma_f16(acc[mt][nt], ah[mt], bl[np] + half * 2);
                        mma_f16(acc[mt][nt], al[mt], bh[np] + half * 2);
                    }
                }
        }
        __syncthreads();
    }

    // ---- epilogue
#pragma unroll
    for (int mt = 0; mt < 2; ++mt) {
        int row0 = m0 + wm * 32 + mt * 16 + trow;
#pragma unroll
        for (int nt = 0; nt < 4; ++nt) {
            int col = n0 + wn * 32 + nt * 8 + 2 * q;
            float b0 = bias[col], b1 = bias[col + 1];
#pragma unroll
            for (int hr = 0; hr < 2; ++hr) {
                size_t mm = (size_t)(row0 + hr * 8);
                size_t orow = PERM ? ((mm & (TT - 1)) * (size_t)BATCH + (mm >> 8)) : mm;
                float2 o;
                o.x = acc[mt][nt][hr * 2 + 0] + b0;
                o.y = acc[mt][nt][hr * 2 + 1] + b1;
                *(float2*)(C + orow * (size_t)GG + col) = o;
            }
        }
    }
}

// ---------------------------------------------------------------------------
// Persistent LSTM layer, fp16 split mma + ldmatrix, 1 sync per k-chunk.
// 256 blocks (16 batch x 16 h chunks), 256 thr = 8 warps (4M x 2N).
// ---------------------------------------------------------------------------
__global__ __launch_bounds__(256, 2) void lstm_rec_tc(
    const float* __restrict__ xz,      // [T][B][G] fp32
    const float* __restrict__ U,       // [H][G] fp32
    __half* __restrict__ seqH,         // [T][B][H] or null
    __half* __restrict__ seqL)
{
    extern __shared__ __align__(16) unsigned smw[];
    unsigned* Uh32 = smw;                  // 64 x 132 words  (byte off 0)
    unsigned* Ul32 = smw + 8448;           // (byte off 33792)
    unsigned* HhB[2] = {smw + 16896, smw + 19456};   // byte 67584 / 77824
    unsigned* HlB[2] = {smw + 18176, smw + 20736};   // byte 72704 / 82944
    __half* UhE = (__half*)Uh32;
    __half* UlE = (__half*)Ul32;

    const int tid  = threadIdx.x;
    const int lane = tid & 31;
    const int w    = tid >> 5;
    const int wm   = w & 3, wn = w >> 2;
    const int trow = lane >> 2, q = lane & 3;
    const int bi   = blockIdx.x >> 4;
    const int hj   = blockIdx.x & 15;

    // ---- load + split U slice, gate-permuted: n_local -> (wn, gate, h')
    for (int idx = tid; idx < 64 * 256; idx += 256) {
        int n = idx & 63, k = idx >> 6;
        int gcol = ((n >> 3) & 3) * HH + hj * 16 + (n >> 5) * 8 + (n & 7);
        float v = U[(size_t)k * GG + gcol];
        __half hb, lb;
        splith(v, hb, lb);
        UhE[n * 264 + k] = hb;
        UlE[n * 264 + k] = lb;
    }
    // ---- zero h-state buffer 0 (this block's cols)
    {
        int r = tid >> 2, c0 = (tid & 3) * 4;
        uint2 z = make_uint2(0u, 0u);
        *(uint2*)&g_hbh[0][(size_t)(bi * 64 + r) * HH + hj * 16 + c0] = z;
        *(uint2*)&g_hbl[0][(size_t)(bi * 64 + r) * HH + hj * 16 + c0] = z;
    }
    gbar();

    const uint32_t usm = smem_u32(smw);
    const uint32_t hhOff[2] = {67584u, 77824u};
    const uint32_t hlOff[2] = {72704u, 82944u};
    // A frag base (row stride 80B), B frag base (U row stride 528B)
    const uint32_t aofs = (uint32_t)(wm * 16 + (lane & 15)) * 80 + ((lane >> 4) & 1) * 16;
    const uint32_t bofs = (uint32_t)(wn * 32 + ((lane >> 4) & 1) * 8 + (lane & 7)) * 528
                        + ((lane >> 3) & 1) * 16;

    const int hcol0 = hj * 16 + wn * 8 + 2 * q;
    const int srow  = tid >> 2;            // staging row 0..63
    const int skw   = (tid & 3) * 4;       // staging k offset (u32 words)

    float cst[4] = {0.f, 0.f, 0.f, 0.f};

    for (int t = 0; t < TT; ++t) {
        const __half* hinH = g_hbh[t & 1];
        const __half* hinL = g_hbl[t & 1];
        __half* houtH = g_hbh[(t + 1) & 1];
        __half* houtL = g_hbl[(t + 1) & 1];

        // xz prefetch
        float2 xv[2][4];
#pragma unroll
        for (int rr = 0; rr < 2; ++rr) {
            int bgr = bi * 64 + wm * 16 + trow + rr * 8;
            const float* xp = xz + ((size_t)t * BATCH + bgr) * GG + hcol0;
#pragma unroll
            for (int g = 0; g < 4; ++g) xv[rr][g] = *(const float2*)(xp + g * 256);
        }

        const __half* hrowH = hinH + (size_t)(bi * 64 + srow) * HH;
        const __half* hrowL = hinL + (size_t)(bi * 64 + srow) * HH;
        uint4 ph = *(const uint4*)(hrowH + skw * 2);
        uint4 pl = *(const uint4*)(hrowL + skw * 2);

        float acc[4][4];
#pragma unroll
        for (int g = 0; g < 4; ++g)
#pragma unroll
            for (int r = 0; r < 4; ++r) acc[g][r] = 0.0f;

        for (int c = 0; c < 8; ++c) {
            const int cb = c & 1;
            *(uint4*)&HhB[cb][srow * 20 + skw] = ph;
            *(uint4*)&HlB[cb][srow * 20 + skw] = pl;
            if (c < 7) {   // LDG prefetch before the barrier: latency hides under sync+mma
                ph = *(const uint4*)(hrowH + (c + 1) * 32 + skw * 2);
                pl = *(const uint4*)(hrowL + (c + 1) * 32 + skw * 2);
            }
            __syncthreads();   // single barrier per chunk (double buffer)

            const uint32_t ahb = usm + hhOff[cb] + aofs;
            const uint32_t alb = usm + hlOff[cb] + aofs;
#pragma unroll
            for (int s = 0; s < 2; ++s) {
                unsigned ah[4], al[4];
                ldsm_x4(ah, ahb + s * 32);
                ldsm_x4(al, alb + s * 32);
                const uint32_t bko = (uint32_t)(c * 64 + s * 32);
#pragma unroll
                for (int gp = 0; gp < 2; ++gp) {
                    unsigned bh4[4], bl4[4];
                    ldsm_x4(bh4, usm + bofs + gp * 8448 + bko);
                    ldsm_x4(bl4, usm + 33792u + bofs + gp * 8448 + bko);
#pragma unroll
                    for (int half = 0; half < 2; ++half) {
                        int g = gp * 2 + half;
                        mma_f16(acc[g], ah, bh4 + half * 2);
                        mma_f16(acc[g], ah, bl4 + half * 2);
                        mma_f16(acc[g], al, bh4 + half * 2);
                    }
                }
            }
        }

        // epilogue: all four gates of (row, h-pair) live in this lane's regs
#pragma unroll
        for (int rr = 0; rr < 2; ++rr) {
            int bgr = bi * 64 + wm * 16 + trow + rr * 8;
            float hv[2];
#pragma unroll
            for (int pp = 0; pp < 2; ++pp) {
                int a = rr * 2 + pp;
                float zi = acc[0][a] + (pp ? xv[rr][0].y : xv[rr][0].x);
                float zf = acc[1][a] + (pp ? xv[rr][1].y : xv[rr][1].x);
                float zg = acc[2][a] + (pp ? xv[rr][2].y : xv[rr][2].x);
                float zo = acc[3][a] + (pp ? xv[rr][3].y : xv[rr][3].x);
                float cc = sigf(zf) * cst[a] + sigf(zi) * tanhf(zg);
                cst[a] = cc;
                hv[pp] = sigf(zo) * tanhf(cc);
            }
            __half h0h, h0l, h1h, h1l;
            splith(hv[0], h0h, h0l);
            splith(hv[1], h1h, h1l);
            __half2 ph2; ph2.x = h0h; ph2.y = h1h;
            __half2 pl2; pl2.x = h0l; pl2.y = h1l;
            size_t o = (size_t)bgr * HH + hcol0;
            *(__half2*)&houtH[o] = ph2;
            *(__half2*)&houtL[o] = pl2;
            if (seqH) {
                size_t so = ((size_t)t * BATCH + bgr) * HH + hcol0;
                *(__half2*)&seqH[so] = ph2;
                *(__half2*)&seqL[so] = pl2;
            }
        }
        gbar();   // publish h for next step
    }
    // final h in g_hbh/g_hbl[0]
}

// ---------------------------------------------------------------------------
// Head: reconstruct h = hi+lo; logits -> softmax -> water-filling (R2 logic).
// ---------------------------------------------------------------------------
__device__ __forceinline__ float clip01(float x) {
    return fminf(fmaxf(x, 0.0f), 0.1f);
}
__device__ __forceinline__ float wsum(float v) {
#pragma unroll
    for (int o = 16; o > 0; o >>= 1) v += __shfl_xor_sync(0xffffffffu, v, o);
    return v;
}
__device__ __forceinline__ float wmax(float v) {
#pragma unroll
    for (int o = 16; o > 0; o >>= 1) v = fmaxf(v, __shfl_xor_sync(0xffffffffu, v, o));
    return v;
}

__global__ __launch_bounds__(64) void head_kernel(
    const float* __restrict__ Wout, const float* __restrict__ bout,
    float* __restrict__ out)
{
    __shared__ float hsh[HH];
    __shared__ float lg[OO];
    const int b = blockIdx.x;
    const int tid = threadIdx.x;

    for (int i = tid; i < HH; i += 64)
        hsh[i] = __half2float(g_hbh[0][(size_t)b * HH + i])
               + __half2float(g_hbl[0][(size_t)b * HH + i]);
    __syncthreads();

    if (tid < OO) {
        float a = bout[tid];
        for (int k = 0; k < HH; ++k) a = fmaf(hsh[k], Wout[(size_t)k * OO + tid], a);
        lg[tid] = a;
    }
    __syncthreads();

    if (tid < 32) {
        const bool has1 = (tid + 32) < OO;
        float v0 = lg[tid];
        float v1 = has1 ? lg[tid + 32] : -INFINITY;

        float m  = wmax(fmaxf(v0, v1));
        float e0 = expf(v0 - m);
        float e1 = has1 ? expf(v1 - m) : 0.0f;
        float s  = wsum(e0 + e1);
        float w0 = e0 / s, w1 = e1 / s;

        float old0 = w0, old1 = w1;
        float wc0 = clip01(w0), wc1 = clip01(w1);
        bool done = false;

        for (int it = 0; it < 50; ++it) {
            float leftover = wsum((old0 - wc0) + (old1 - wc1));
            bool m0 = (wc0 != 0.1f), m1 = (wc1 != 0.1f);
            float n0 = m0 ? wc0 : 0.0f;
            float n1 = m1 ? wc1 : 0.0f;
            float denom = wsum(n0 + n1);
            float dd = (denom == 0.0f) ? 1.0f : denom;
            float wn0 = m0 ? wc0 + leftover * n0 / dd : wc0;
            float wn1 = m1 ? wc1 + leftover * n1 / dd : wc1;
            bool over = __any_sync(0xffffffffu, (wn0 > 0.1f) || (wn1 > 0.1f));
            bool ndone = !over;
            float wx0 = ndone ? wn0 : clip01(wn0);
            float wx1 = ndone ? wn1 : clip01(wn1);
            if (!done) { old0 = wn0; old1 = wn1; wc0 = wx0; wc1 = wx1; }
            done = done || ndone;
        }

        out[(size_t)b * OO + tid] = wc0;
        if (has1) out[(size_t)b * OO + tid + 32] = wc1;
    }
}

// ---------------------------------------------------------------------------
// Launch (graph-capturable: kernel launches only)
// ---------------------------------------------------------------------------
extern "C" void kernel_launch(void* const* d_in, const int* in_sizes, int n_in,
                              void* d_out, int out_size)
{
    const float* x    = (const float*)d_in[0];
    const float* W0   = (const float*)d_in[1];
    const float* U0   = (const float*)d_in[2];
    const float* b0   = (const float*)d_in[3];
    const float* W1   = (const float*)d_in[4];
    const float* U1   = (const float*)d_in[5];
    const float* b1   = (const float*)d_in[6];
    const float* Wout = (const float*)d_in[7];
    const float* bout = (const float*)d_in[8];
    float* out = (float*)d_out;

    float* p_xz = nullptr;
    __half *p_h0h = nullptr, *p_h0l = nullptr;
    cudaGetSymbolAddress((void**)&p_xz,  g_xz);
    cudaGetSymbolAddress((void**)&p_h0h, g_h0h);
    cudaGetSymbolAddress((void**)&p_h0l, g_h0l);

    const int REC_SMEM = 88064;   // U hi/lo (67584) + h chunk dbl-buf (20480)
    cudaFuncSetAttribute(lstm_rec_tc, cudaFuncAttributeMaxDynamicSharedMemorySize, REC_SMEM);

    dim3 gg(GG / 64, (BATCH * TT) / 128);   // (16, 2048)

    // Layer 0 input projection: xz0[t][b][g]
    gemm_f16<true, false><<<gg, 256>>>(x, nullptr, nullptr, W0, b0, p_xz, FF);
    // Layer 0 recurrence -> pre-split h0seq planes
    lstm_rec_tc<<<256, 256, REC_SMEM>>>(p_xz, U0, p_h0h, p_h0l);
    // Layer 1 input projection (A pre-split, reuses g_xz)
    gemm_f16<false, true><<<gg, 256>>>(nullptr, p_h0h, p_h0l, W1, b1, p_xz, HH);
    // Layer 1 recurrence (final h ends in g_hbh/g_hbl[0])
    lstm_rec_tc<<<256, 256, REC_SMEM>>>(p_xz, U1, nullptr, nullptr);
    // Head: logits -> softmax -> rebalance
    head_kernel<<<BATCH, 64>>>(Wout, bout, out);
}